// round 14
// baseline (speedup 1.0000x reference)
#include <cuda_runtime.h>
#include <cuda_fp16.h>
#include <mma.h>
#include <cstdint>

using namespace nvcuda;

// NOTE (environment pitfalls, confirmed):
//  - Harness PTX targets sm_103 (no 'a'): tcgen05/TMEM rejected by ptxas.
//    Legacy mma.sync (HMMA) is the usable tensor engine.
//  - Static __device__ scratch: 68MB passes, 142MB poisons. Stay <100MB.
//  - Winning GEMM shape: 8 warps, 128x128 tile, 4x2 warp grid, double
//    buffered sync loads, 2 CTAs/SM, fp16 operands + fp32 accum.
//    This round: K=32 stages (half the barriers) + X->fp16 fused into sv.

// ---------------- problem constants ----------------
#define BQ 4
#define LQ 8192
#define DQ 1024
#define NHQ 16
#define HDQ 64
#define MT (BQ * LQ)          // 32768 rows
#define ROW_TILES (MT / 128)  // 256
#define COL_TILES (DQ / 128)  // 8
#define NST 32                // k-stages of 32

// ---------------- device scratch (no allocations allowed) ----------------
__device__ __align__(16) __half g_Xh[MT * DQ];       // fp16 copy of query (64MB)
__device__ __align__(16) __half g_Wkh[DQ * DQ];      // fp16 Wk (2MB)
__device__ __align__(16) __half g_Wqh[DQ * DQ];      // fp16 Wq (2MB)
__device__ __align__(16) float g_Wv_sumT[NHQ * DQ];  // [head][k]
__device__ __align__(16) float g_bv_sum[NHQ];
__device__ __align__(16) int   g_mask[MT];
__device__ int   g_mask_kind;
__device__ __align__(16) float g_sv[MT * NHQ];
__device__ __align__(16) float g_partial[ROW_TILES * DQ];
__device__ __align__(16) float g_kv_sum[BQ * DQ];

__device__ __forceinline__ float phi_fn(float x) {
    return x > 0.f ? x + 1.f : __expf(x);   // elu(x)+1
}

__device__ __forceinline__ uint2 pack_half4(float4 v) {
    __half2 h01 = __floats2half2_rn(v.x, v.y);
    __half2 h23 = __floats2half2_rn(v.z, v.w);
    uint2 u;
    u.x = *reinterpret_cast<const uint32_t*>(&h01);
    u.y = *reinterpret_cast<const uint32_t*>(&h23);
    return u;
}

// ---------------- fp32 -> fp16 conversion (weights) ----------------
__global__ void tohalf_kernel(const float* __restrict__ src, __half* __restrict__ dst) {
    int i = blockIdx.x * 256 + threadIdx.x;
    float4 a = ((const float4*)src)[i * 2];
    float4 b = ((const float4*)src)[i * 2 + 1];
    uint2 u0 = pack_half4(a), u1 = pack_half4(b);
    uint4 u; u.x = u0.x; u.y = u0.y; u.z = u1.x; u.w = u1.y;
    ((uint4*)dst)[i] = u;
}

// ---------------- mask dtype detection + normalization ----------------
__global__ void detect_mask_kernel(const unsigned int* m) {
    __shared__ int f_nonbin, f_float;
    if (threadIdx.x == 0) { f_nonbin = 0; f_float = 0; }
    __syncthreads();
    int nb = 0, fl = 0;
    for (int i = threadIdx.x; i < 8192; i += 256) {
        unsigned v = m[i];
        if (v == 0x3F800000u) fl = 1;
        else if (v > 1u) nb = 1;
    }
    if (fl) atomicOr(&f_float, 1);
    if (nb) atomicOr(&f_nonbin, 1);
    __syncthreads();
    if (threadIdx.x == 0) g_mask_kind = f_float ? 2 : (f_nonbin ? 1 : 0);
}

__global__ void normalize_mask_kernel(const void* m) {
    int i = blockIdx.x * 256 + threadIdx.x;
    if (i >= MT) return;
    int kind = g_mask_kind;
    int v;
    if (kind == 2)      v = (((const float*)m)[i] != 0.0f);
    else if (kind == 1) v = (((const unsigned char*)m)[i] != 0);
    else                v = (((const int*)m)[i] != 0);
    g_mask[i] = v;
}

// ---------------- Wv column sums per head (transposed) ----------------
__global__ void wvsum_kernel(const float* __restrict__ Wv,
                             const float* __restrict__ bv) {
    int t = blockIdx.x * 256 + threadIdx.x;
    if (t < DQ * NHQ) {
        int k = t >> 4, n = t & 15;
        const float* p = Wv + (size_t)k * DQ + n * HDQ;
        float s = 0.f;
        #pragma unroll 8
        for (int v = 0; v < HDQ; v++) s += p[v];
        g_Wv_sumT[n * DQ + k] = s;
    }
    if (t < NHQ) {
        const float* p = bv + t * HDQ;
        float s = 0.f;
        #pragma unroll 8
        for (int v = 0; v < HDQ; v++) s += p[v];
        g_bv_sum[t] = s;
    }
}

// ---------------- sv pre-pass + fused X->fp16 conversion ----------------
__global__ void __launch_bounds__(256) sv_kernel(const float* __restrict__ X,
                                                 __half* __restrict__ Xh) {
    extern __shared__ __align__(16) float4 sWv[];
    const int tid = threadIdx.x;
    {
        const float4* src = (const float4*)g_Wv_sumT;
        #pragma unroll
        for (int i = 0; i < NHQ * DQ / 4 / 256; i++)
            sWv[i * 256 + tid] = src[i * 256 + tid];
    }
    __syncthreads();

    const int warp = tid >> 5, lane = tid & 31;
    const int row0 = blockIdx.x * 16 + warp * 2;
    const float4* x0 = (const float4*)(X + (size_t)row0 * DQ);
    const float4* x1 = (const float4*)(X + (size_t)(row0 + 1) * DQ);
    uint2* xh0 = (uint2*)(Xh + (size_t)row0 * DQ);
    uint2* xh1 = (uint2*)(Xh + (size_t)(row0 + 1) * DQ);

    float acc[2][NHQ];
    #pragma unroll
    for (int p = 0; p < 2; p++)
        #pragma unroll
        for (int h = 0; h < NHQ; h++) acc[p][h] = 0.f;

    for (int c = lane; c < DQ / 4; c += 32) {
        float4 xv0 = x0[c], xv1 = x1[c];
        xh0[c] = pack_half4(xv0);            // fused fp16 writeout
        xh1[c] = pack_half4(xv1);
        #pragma unroll
        for (int h = 0; h < NHQ; h++) {
            float4 w = sWv[h * (DQ / 4) + c];
            acc[0][h] += xv0.x * w.x + xv0.y * w.y + xv0.z * w.z + xv0.w * w.w;
            acc[1][h] += xv1.x * w.x + xv1.y * w.y + xv1.z * w.z + xv1.w * w.w;
        }
    }
    #pragma unroll
    for (int off = 16; off; off >>= 1)
        #pragma unroll
        for (int p = 0; p < 2; p++)
            #pragma unroll
            for (int h = 0; h < NHQ; h++)
                acc[p][h] += __shfl_xor_sync(0xffffffffu, acc[p][h], off);
    if (lane < NHQ) {
        float bvs = g_bv_sum[lane];
        #pragma unroll
        for (int p = 0; p < 2; p++) {
            int m = g_mask[row0 + p];
            g_sv[(size_t)(row0 + p) * NHQ + lane] = m ? 0.f : acc[p][lane] + bvs;
        }
    }
}

// ---------------- main GEMM: 128x128 tile, fp16 HMMA, K=32 stages ----------
#define AS_LDH 40
#define BS_LDH 136
#define A_STG_H (128 * AS_LDH)               // 5120 halves
#define B_STG_H (32 * BS_LDH)                // 4352 halves
#define B_BASE_H (2 * A_STG_H)               // 10240
#define STAGES_H (B_BASE_H + 2 * B_STG_H)    // 18944 halves = 37888 B
#define CT_LD 68
#define GSMEM_B (STAGES_H * 2)               // 37888 B (> Ct 34816 B)

template <int MODE>
__global__ void __launch_bounds__(256, 2)
gemm_kernel(const __half* __restrict__ Xh, const __half* __restrict__ Wh,
            const float* __restrict__ bias, float* __restrict__ outp) {
    extern __shared__ __align__(16) char ds[];
    __half* hs = (__half*)ds;            // stages
    float*  Ct = (float*)ds;             // epilogue union
    __shared__ float svred[256];
    __shared__ float red2[256];

    const int tid = threadIdx.x;
    const int bn = blockIdx.x;   // column tile (128 cols = 2 heads)
    const int br = blockIdx.y;   // row tile

    const __half* Ab = Xh + (size_t)br * 128 * DQ;
    const __half* Bb = Wh + bn * 128;

    // A staging: thread owns row arow, 16 halves at aseg (2 x uint4)
    const int arow = tid >> 1, aseg = (tid & 1) * 16;
    // B staging: thread owns k-row brow (0..31), 16 halves at bseg
    const int brow = tid >> 3, bseg = (tid & 7) * 16;
    const __half* srcA = Ab + (size_t)arow * DQ + aseg;
    const __half* srcB = Bb + (size_t)brow * DQ + bseg;
    __half* dstA = hs + arow * AS_LDH + aseg;
    __half* dstB = hs + B_BASE_H + brow * BS_LDH + bseg;

    const int wid = tid >> 5;
    const int wm = wid & 3;       // warp rows wm*32 .. +31
    const int wn = wid >> 2;      // warp cols wn*64 .. +63

    wmma::fragment<wmma::accumulator, 16, 16, 16, float> fc[2][4];
    #pragma unroll
    for (int i = 0; i < 2; i++)
        #pragma unroll
        for (int j = 0; j < 4; j++)
            wmma::fill_fragment(fc[i][j], 0.f);

    // ---- preload stage 0 ----
    {
        *(uint4*)dstA       = *(const uint4*)(srcA);
        *(uint4*)(dstA + 8) = *(const uint4*)(srcA + 8);
        *(uint4*)dstB       = *(const uint4*)(srcB);
        *(uint4*)(dstB + 8) = *(const uint4*)(srcB + 8);
    }
    __syncthreads();

    int buf = 0;
    for (int t = 0; t < NST; t++) {
        uint4 na0, na1, nb0, nb1;
        if (t < NST - 1) {
            const int ko = (t + 1) * 32;
            na0 = *(const uint4*)(srcA + ko);
            na1 = *(const uint4*)(srcA + ko + 8);
            nb0 = *(const uint4*)(srcB + (size_t)ko * DQ);
            nb1 = *(const uint4*)(srcB + (size_t)ko * DQ + 8);
        }

        // compute on stage[buf]: two K=16 wmma steps
        {
            const __half* As = hs + buf * A_STG_H;
            const __half* Bs = hs + B_BASE_H + buf * B_STG_H;
            #pragma unroll
            for (int kk = 0; kk < 2; kk++) {
                wmma::fragment<wmma::matrix_a, 16, 16, 16, __half, wmma::row_major> fa[2];
                wmma::fragment<wmma::matrix_b, 16, 16, 16, __half, wmma::row_major> fb[4];
                #pragma unroll
                for (int i = 0; i < 2; i++)
                    wmma::load_matrix_sync(fa[i], As + (wm * 32 + i * 16) * AS_LDH + kk * 16, AS_LDH);
                #pragma unroll
                for (int j = 0; j < 4; j++)
                    wmma::load_matrix_sync(fb[j], Bs + (kk * 16) * BS_LDH + wn * 64 + j * 16, BS_LDH);
                #pragma unroll
                for (int i = 0; i < 2; i++)
                    #pragma unroll
                    for (int j = 0; j < 4; j++)
                        wmma::mma_sync(fc[i][j], fa[i], fb[j], fc[i][j]);
            }
        }

        if (t < NST - 1) {
            const int nbuf = buf ^ 1;
            *(uint4*)(dstA + nbuf * A_STG_H)     = na0;
            *(uint4*)(dstA + nbuf * A_STG_H + 8) = na1;
            *(uint4*)(dstB + nbuf * B_STG_H)     = nb0;
            *(uint4*)(dstB + nbuf * B_STG_H + 8) = nb1;
        }
        __syncthreads();
        buf ^= 1;
    }

    // ---- epilogue (identical math to round 13) ----
    if (MODE == 0) {
        if (tid < 128) {
            float2 s = *(const float2*)(g_sv + (size_t)(br * 128 + tid) * NHQ + bn * 2);
            svred[tid * 2 + 0] = s.x;
            svred[tid * 2 + 1] = s.y;
        }
        #pragma unroll
        for (int hh = 0; hh < 2; hh++) {
            __syncthreads();
            if (wn == hh) {
                #pragma unroll
                for (int i = 0; i < 2; i++)
                    #pragma unroll
                    for (int j = 0; j < 4; j++)
                        wmma::store_matrix_sync(&Ct[(wm * 32 + i * 16) * CT_LD + j * 16],
                                                fc[i][j], CT_LD, wmma::mem_row_major);
            }
            __syncthreads();
            int c = tid & 63, rg = tid >> 6;
            float bias_c = bias[bn * 128 + hh * 64 + c];
            float part = 0.f;
            #pragma unroll 8
            for (int r = rg; r < 128; r += 4) {
                float x = Ct[r * CT_LD + c] + bias_c;
                part += phi_fn(x) * svred[r * 2 + hh];
            }
            red2[rg * 64 + c] = part;
            __syncthreads();
            if (tid < 64) {
                float tot = red2[tid] + red2[64 + tid] + red2[128 + tid] + red2[192 + tid];
                g_partial[(size_t)br * DQ + bn * 128 + hh * 64 + tid] = tot;
            }
        }
    } else {
        int b = br >> 6;
        #pragma unroll
        for (int hh = 0; hh < 2; hh++) {
            __syncthreads();
            if (wn == hh) {
                #pragma unroll
                for (int i = 0; i < 2; i++)
                    #pragma unroll
                    for (int j = 0; j < 4; j++)
                        wmma::store_matrix_sync(&Ct[(wm * 32 + i * 16) * CT_LD + j * 16],
                                                fc[i][j], CT_LD, wmma::mem_row_major);
            }
            __syncthreads();
            int c = tid & 63, rg = tid >> 6;
            int gcol = bn * 128 + hh * 64 + c;
            float bias_c = bias[gcol];
            float kvs = g_kv_sum[b * DQ + gcol];
            #pragma unroll 8
            for (int r = rg; r < 128; r += 4) {
                float x = Ct[r * CT_LD + c] + bias_c;
                outp[(size_t)(br * 128 + r) * DQ + gcol] = phi_fn(x) * kvs;
            }
        }
    }
}

// ---------------- deterministic reduction of per-tile partials ----------------
__global__ void kvreduce_kernel() {
    int t = blockIdx.x * 256 + threadIdx.x;
    if (t >= BQ * DQ) return;
    int b = t >> 10, c = t & 1023;
    const float* p = g_partial + (size_t)(b * 64) * DQ + c;
    float s = 0.f;
    #pragma unroll 8
    for (int j = 0; j < 64; j++) s += p[(size_t)j * DQ];
    g_kv_sum[t] = s;
}

// ---------------- entry point ----------------
extern "C" void kernel_launch(void* const* d_in, const int* in_sizes, int n_in,
                              void* d_out, int out_size) {
    const float* query = (const float*)d_in[0];
    const void*  mask  = d_in[1];
    const float* Wq    = (const float*)d_in[2];
    const float* bq    = (const float*)d_in[3];
    const float* Wk    = (const float*)d_in[4];
    const float* bk    = (const float*)d_in[5];
    const float* Wv    = (const float*)d_in[6];
    const float* bv    = (const float*)d_in[7];
    float* out = (float*)d_out;

    __half* xh;  cudaGetSymbolAddress((void**)&xh,  g_Xh);
    __half* wkh; cudaGetSymbolAddress((void**)&wkh, g_Wkh);
    __half* wqh; cudaGetSymbolAddress((void**)&wqh, g_Wqh);

    const int sv_smem = NHQ * DQ * 4;   // 64KB
    cudaFuncSetAttribute(sv_kernel, cudaFuncAttributeMaxDynamicSharedMemorySize, sv_smem);
    cudaFuncSetAttribute(gemm_kernel<0>, cudaFuncAttributeMaxDynamicSharedMemorySize, GSMEM_B);
    cudaFuncSetAttribute(gemm_kernel<1>, cudaFuncAttributeMaxDynamicSharedMemorySize, GSMEM_B);

    detect_mask_kernel<<<1, 256>>>((const unsigned int*)mask);
    normalize_mask_kernel<<<MT / 256, 256>>>(mask);
    wvsum_kernel<<<(DQ * NHQ + 255) / 256, 256>>>(Wv, bv);
    tohalf_kernel<<<DQ * DQ / 8 / 256, 256>>>(Wk, wkh);
    tohalf_kernel<<<DQ * DQ / 8 / 256, 256>>>(Wq, wqh);
    sv_kernel<<<MT / 16, 256, sv_smem>>>(query, xh);
    gemm_kernel<0><<<dim3(COL_TILES, ROW_TILES), 256, GSMEM_B>>>(xh, wkh, bk, nullptr);
    kvreduce_kernel<<<(BQ * DQ + 255) / 256, 256>>>();
    gemm_kernel<1><<<dim3(COL_TILES, ROW_TILES), 256, GSMEM_B>>>(xh, wqh, bq, out);
}

// round 15
// speedup vs baseline: 1.0670x; 1.0670x over previous
#include <cuda_runtime.h>
#include <cuda_fp16.h>
#include <mma.h>
#include <cstdint>

using namespace nvcuda;

// NOTE (environment pitfalls, confirmed):
//  - Harness PTX targets sm_103 (no 'a'): tcgen05/TMEM rejected by ptxas.
//    Legacy mma.sync (HMMA) is the usable tensor engine.
//  - Static __device__ scratch: 68MB passes, 142MB poisons. Stay <100MB.
//  - Winning GEMM shape (do not touch): 8 warps, 128x128 tile, 4x2 warp
//    grid, K=16 double-buffered sync-load stages (AS_LDH=24), 2 CTAs/SM,
//    fp16 operands + fp32 accum. K=32/AS_LDH=40 regressed (bank conflicts).
//  - X->fp16 fused into sv_kernel: good (-28us tohalf pass).

// ---------------- problem constants ----------------
#define BQ 4
#define LQ 8192
#define DQ 1024
#define NHQ 16
#define HDQ 64
#define MT (BQ * LQ)          // 32768 rows
#define ROW_TILES (MT / 128)  // 256
#define COL_TILES (DQ / 128)  // 8
#define NT 64                 // k-stages of 16

// ---------------- device scratch (no allocations allowed) ----------------
__device__ __align__(16) __half g_Xh[MT * DQ];       // fp16 copy of query (64MB)
__device__ __align__(16) __half g_Wkh[DQ * DQ];      // fp16 Wk (2MB)
__device__ __align__(16) __half g_Wqh[DQ * DQ];      // fp16 Wq (2MB)
__device__ __align__(16) float g_Wv_sumT[NHQ * DQ];  // [head][k]
__device__ __align__(16) float g_bv_sum[NHQ];
__device__ __align__(16) int   g_mask[MT];
__device__ int   g_mask_kind;
__device__ __align__(16) float g_sv[MT * NHQ];
__device__ __align__(16) float g_partial[ROW_TILES * DQ];
__device__ __align__(16) float g_kv_sum[BQ * DQ];

__device__ __forceinline__ float phi_fn(float x) {
    return x > 0.f ? x + 1.f : __expf(x);   // elu(x)+1
}

__device__ __forceinline__ uint2 pack_half4(float4 v) {
    __half2 h01 = __floats2half2_rn(v.x, v.y);
    __half2 h23 = __floats2half2_rn(v.z, v.w);
    uint2 u;
    u.x = *reinterpret_cast<const uint32_t*>(&h01);
    u.y = *reinterpret_cast<const uint32_t*>(&h23);
    return u;
}

// ---------------- fp32 -> fp16 conversion (weights) ----------------
__global__ void tohalf_kernel(const float* __restrict__ src, __half* __restrict__ dst) {
    int i = blockIdx.x * 256 + threadIdx.x;
    float4 a = ((const float4*)src)[i * 2];
    float4 b = ((const float4*)src)[i * 2 + 1];
    uint2 u0 = pack_half4(a), u1 = pack_half4(b);
    uint4 u; u.x = u0.x; u.y = u0.y; u.z = u1.x; u.w = u1.y;
    ((uint4*)dst)[i] = u;
}

// ---------------- mask dtype detection + normalization ----------------
__global__ void detect_mask_kernel(const unsigned int* m) {
    __shared__ int f_nonbin, f_float;
    if (threadIdx.x == 0) { f_nonbin = 0; f_float = 0; }
    __syncthreads();
    int nb = 0, fl = 0;
    for (int i = threadIdx.x; i < 8192; i += 256) {
        unsigned v = m[i];
        if (v == 0x3F800000u) fl = 1;
        else if (v > 1u) nb = 1;
    }
    if (fl) atomicOr(&f_float, 1);
    if (nb) atomicOr(&f_nonbin, 1);
    __syncthreads();
    if (threadIdx.x == 0) g_mask_kind = f_float ? 2 : (f_nonbin ? 1 : 0);
}

__global__ void normalize_mask_kernel(const void* m) {
    int i = blockIdx.x * 256 + threadIdx.x;
    if (i >= MT) return;
    int kind = g_mask_kind;
    int v;
    if (kind == 2)      v = (((const float*)m)[i] != 0.0f);
    else if (kind == 1) v = (((const unsigned char*)m)[i] != 0);
    else                v = (((const int*)m)[i] != 0);
    g_mask[i] = v;
}

// ---------------- Wv column sums per head (transposed) ----------------
__global__ void wvsum_kernel(const float* __restrict__ Wv,
                             const float* __restrict__ bv) {
    int t = blockIdx.x * 256 + threadIdx.x;
    if (t < DQ * NHQ) {
        int k = t >> 4, n = t & 15;
        const float* p = Wv + (size_t)k * DQ + n * HDQ;
        float s = 0.f;
        #pragma unroll 8
        for (int v = 0; v < HDQ; v++) s += p[v];
        g_Wv_sumT[n * DQ + k] = s;
    }
    if (t < NHQ) {
        const float* p = bv + t * HDQ;
        float s = 0.f;
        #pragma unroll 8
        for (int v = 0; v < HDQ; v++) s += p[v];
        g_bv_sum[t] = s;
    }
}

// ---------------- sv pre-pass + fused X->fp16 conversion ----------------
__global__ void __launch_bounds__(256) sv_kernel(const float* __restrict__ X,
                                                 __half* __restrict__ Xh) {
    extern __shared__ __align__(16) float4 sWv[];
    const int tid = threadIdx.x;
    {
        const float4* src = (const float4*)g_Wv_sumT;
        #pragma unroll
        for (int i = 0; i < NHQ * DQ / 4 / 256; i++)
            sWv[i * 256 + tid] = src[i * 256 + tid];
    }
    __syncthreads();

    const int warp = tid >> 5, lane = tid & 31;
    const int row0 = blockIdx.x * 16 + warp * 2;
    const float4* x0 = (const float4*)(X + (size_t)row0 * DQ);
    const float4* x1 = (const float4*)(X + (size_t)(row0 + 1) * DQ);
    uint2* xh0 = (uint2*)(Xh + (size_t)row0 * DQ);
    uint2* xh1 = (uint2*)(Xh + (size_t)(row0 + 1) * DQ);

    float acc[2][NHQ];
    #pragma unroll
    for (int p = 0; p < 2; p++)
        #pragma unroll
        for (int h = 0; h < NHQ; h++) acc[p][h] = 0.f;

    for (int c = lane; c < DQ / 4; c += 32) {
        float4 xv0 = x0[c], xv1 = x1[c];
        xh0[c] = pack_half4(xv0);            // fused fp16 writeout
        xh1[c] = pack_half4(xv1);
        #pragma unroll
        for (int h = 0; h < NHQ; h++) {
            float4 w = sWv[h * (DQ / 4) + c];
            acc[0][h] += xv0.x * w.x + xv0.y * w.y + xv0.z * w.z + xv0.w * w.w;
            acc[1][h] += xv1.x * w.x + xv1.y * w.y + xv1.z * w.z + xv1.w * w.w;
        }
    }
    #pragma unroll
    for (int off = 16; off; off >>= 1)
        #pragma unroll
        for (int p = 0; p < 2; p++)
            #pragma unroll
            for (int h = 0; h < NHQ; h++)
                acc[p][h] += __shfl_xor_sync(0xffffffffu, acc[p][h], off);
    if (lane < NHQ) {
        float bvs = g_bv_sum[lane];
        #pragma unroll
        for (int p = 0; p < 2; p++) {
            int m = g_mask[row0 + p];
            g_sv[(size_t)(row0 + p) * NHQ + lane] = m ? 0.f : acc[p][lane] + bvs;
        }
    }
}

// ---------------- main GEMM: round-13 exact shape (K=16, AS_LDH=24) --------
#define AS_LDH 24
#define BS_LDH 136
#define A_STG_H (128 * AS_LDH)               // 3072 halves
#define B_STG_H (16 * BS_LDH)                // 2176 halves
#define B_BASE_H (2 * A_STG_H)               // 6144
#define CT_LD 68
#define GSMEM_B (128 * CT_LD * 4)            // 34816 B (union covers stages)

template <int MODE>
__global__ void __launch_bounds__(256, 2)
gemm_kernel(const __half* __restrict__ Xh, const __half* __restrict__ Wh,
            const float* __restrict__ bias, float* __restrict__ outp) {
    extern __shared__ __align__(16) char ds[];
    __half* hs = (__half*)ds;            // stages
    float*  Ct = (float*)ds;             // epilogue union
    __shared__ float svred[256];
    __shared__ float red2[256];

    const int tid = threadIdx.x;
    const int bn = blockIdx.x;   // column tile (128 cols = 2 heads)
    const int br = blockIdx.y;   // row tile

    const __half* Ab = Xh + (size_t)br * 128 * DQ;
    const __half* Bb = Wh + bn * 128;

    // A staging: thread owns row arow, 8 halves at aseg
    const int arow = tid >> 1, aseg = (tid & 1) * 8;
    // B staging: thread owns row brow, 8 halves at bseg
    const int brow = tid >> 4, bseg = (tid & 15) * 8;
    const __half* srcA = Ab + (size_t)arow * DQ + aseg;
    const __half* srcB = Bb + (size_t)brow * DQ + bseg;
    __half* dstA = hs + arow * AS_LDH + aseg;
    __half* dstB = hs + B_BASE_H + brow * BS_LDH + bseg;

    const int wid = tid >> 5;
    const int wm = wid & 3;       // warp rows wm*32 .. +31
    const int wn = wid >> 2;      // warp cols wn*64 .. +63

    wmma::fragment<wmma::accumulator, 16, 16, 16, float> fc[2][4];
    #pragma unroll
    for (int i = 0; i < 2; i++)
        #pragma unroll
        for (int j = 0; j < 4; j++)
            wmma::fill_fragment(fc[i][j], 0.f);

    // ---- preload stage 0 ----
    {
        uint4 a = *(const uint4*)(srcA);
        uint4 b = *(const uint4*)(srcB);
        *(uint4*)dstA = a;
        *(uint4*)dstB = b;
    }
    __syncthreads();

    int buf = 0;
    for (int t = 0; t < NT; t++) {
        uint4 na, nb;
        if (t < NT - 1) {
            const int ko = (t + 1) * 16;
            na = *(const uint4*)(srcA + ko);
            nb = *(const uint4*)(srcB + (size_t)ko * DQ);
        }

        // compute on stage[buf]: one K=16 wmma step
        {
            const __half* As = hs + buf * A_STG_H;
            const __half* Bs = hs + B_BASE_H + buf * B_STG_H;
            wmma::fragment<wmma::matrix_a, 16, 16, 16, __half, wmma::row_major> fa[2];
            wmma::fragment<wmma::matrix_b, 16, 16, 16, __half, wmma::row_major> fb[4];
            #pragma unroll
            for (int i = 0; i < 2; i++)
                wmma::load_matrix_sync(fa[i], As + (wm * 32 + i * 16) * AS_LDH, AS_LDH);
            #pragma unroll
            for (int j = 0; j < 4; j++)
                wmma::load_matrix_sync(fb[j], Bs + wn * 64 + j * 16, BS_LDH);
            #pragma unroll
            for (int i = 0; i < 2; i++)
                #pragma unroll
                for (int j = 0; j < 4; j++)
                    wmma::mma_sync(fc[i][j], fa[i], fb[j], fc[i][j]);
        }

        if (t < NT - 1) {
            const int nbuf = buf ^ 1;
            *(uint4*)(dstA + nbuf * A_STG_H) = na;
            *(uint4*)(dstB + nbuf * B_STG_H) = nb;
        }
        __syncthreads();
        buf ^= 1;
    }

    // ---- epilogue (identical math to round 13) ----
    if (MODE == 0) {
        if (tid < 128) {
            float2 s = *(const float2*)(g_sv + (size_t)(br * 128 + tid) * NHQ + bn * 2);
            svred[tid * 2 + 0] = s.x;
            svred[tid * 2 + 1] = s.y;
        }
        #pragma unroll
        for (int hh = 0; hh < 2; hh++) {
            __syncthreads();
            if (wn == hh) {
                #pragma unroll
                for (int i = 0; i < 2; i++)
                    #pragma unroll
                    for (int j = 0; j < 4; j++)
                        wmma::store_matrix_sync(&Ct[(wm * 32 + i * 16) * CT_LD + j * 16],
                                                fc[i][j], CT_LD, wmma::mem_row_major);
            }
            __syncthreads();
            int c = tid & 63, rg = tid >> 6;
            float bias_c = bias[bn * 128 + hh * 64 + c];
            float part = 0.f;
            #pragma unroll 8
            for (int r = rg; r < 128; r += 4) {
                float x = Ct[r * CT_LD + c] + bias_c;
                part += phi_fn(x) * svred[r * 2 + hh];
            }
            red2[rg * 64 + c] = part;
            __syncthreads();
            if (tid < 64) {
                float tot = red2[tid] + red2[64 + tid] + red2[128 + tid] + red2[192 + tid];
                g_partial[(size_t)br * DQ + bn * 128 + hh * 64 + tid] = tot;
            }
        }
    } else {
        int b = br >> 6;
        #pragma unroll
        for (int hh = 0; hh < 2; hh++) {
            __syncthreads();
            if (wn == hh) {
                #pragma unroll
                for (int i = 0; i < 2; i++)
                    #pragma unroll
                    for (int j = 0; j < 4; j++)
                        wmma::store_matrix_sync(&Ct[(wm * 32 + i * 16) * CT_LD + j * 16],
                                                fc[i][j], CT_LD, wmma::mem_row_major);
            }
            __syncthreads();
            int c = tid & 63, rg = tid >> 6;
            int gcol = bn * 128 + hh * 64 + c;
            float bias_c = bias[gcol];
            float kvs = g_kv_sum[b * DQ + gcol];
            #pragma unroll 8
            for (int r = rg; r < 128; r += 4) {
                float x = Ct[r * CT_LD + c] + bias_c;
                outp[(size_t)(br * 128 + r) * DQ + gcol] = phi_fn(x) * kvs;
            }
        }
    }
}

// ---------------- deterministic reduction of per-tile partials ----------------
__global__ void kvreduce_kernel() {
    int t = blockIdx.x * 256 + threadIdx.x;
    if (t >= BQ * DQ) return;
    int b = t >> 10, c = t & 1023;
    const float* p = g_partial + (size_t)(b * 64) * DQ + c;
    float s = 0.f;
    #pragma unroll 8
    for (int j = 0; j < 64; j++) s += p[(size_t)j * DQ];
    g_kv_sum[t] = s;
}

// ---------------- entry point ----------------
extern "C" void kernel_launch(void* const* d_in, const int* in_sizes, int n_in,
                              void* d_out, int out_size) {
    const float* query = (const float*)d_in[0];
    const void*  mask  = d_in[1];
    const float* Wq    = (const float*)d_in[2];
    const float* bq    = (const float*)d_in[3];
    const float* Wk    = (const float*)d_in[4];
    const float* bk    = (const float*)d_in[5];
    const float* Wv    = (const float*)d_in[6];
    const float* bv    = (const float*)d_in[7];
    float* out = (float*)d_out;

    __half* xh;  cudaGetSymbolAddress((void**)&xh,  g_Xh);
    __half* wkh; cudaGetSymbolAddress((void**)&wkh, g_Wkh);
    __half* wqh; cudaGetSymbolAddress((void**)&wqh, g_Wqh);

    const int sv_smem = NHQ * DQ * 4;   // 64KB
    cudaFuncSetAttribute(sv_kernel, cudaFuncAttributeMaxDynamicSharedMemorySize, sv_smem);
    cudaFuncSetAttribute(gemm_kernel<0>, cudaFuncAttributeMaxDynamicSharedMemorySize, GSMEM_B);
    cudaFuncSetAttribute(gemm_kernel<1>, cudaFuncAttributeMaxDynamicSharedMemorySize, GSMEM_B);

    detect_mask_kernel<<<1, 256>>>((const unsigned int*)mask);
    normalize_mask_kernel<<<MT / 256, 256>>>(mask);
    wvsum_kernel<<<(DQ * NHQ + 255) / 256, 256>>>(Wv, bv);
    tohalf_kernel<<<DQ * DQ / 8 / 256, 256>>>(Wk, wkh);
    tohalf_kernel<<<DQ * DQ / 8 / 256, 256>>>(Wq, wqh);
    sv_kernel<<<MT / 16, 256, sv_smem>>>(query, xh);
    gemm_kernel<0><<<dim3(COL_TILES, ROW_TILES), 256, GSMEM_B>>>(xh, wkh, bk, nullptr);
    kvreduce_kernel<<<(BQ * DQ + 255) / 256, 256>>>();
    gemm_kernel<1><<<dim3(COL_TILES, ROW_TILES), 256, GSMEM_B>>>(xh, wqh, bq, out);
}

// round 16
// speedup vs baseline: 1.0746x; 1.0071x over previous
#include <cuda_runtime.h>
#include <cuda_fp16.h>
#include <mma.h>
#include <cstdint>

using namespace nvcuda;

// NOTE (environment pitfalls, confirmed):
//  - Harness PTX targets sm_103 (no 'a'): tcgen05/TMEM rejected by ptxas.
//    Legacy mma.sync (HMMA) is the usable tensor engine.
//  - Static __device__ scratch: 68MB passes, 142MB poisons. Stay <100MB.
//  - ncu profiles the launch at INDEX 3. Launch order is arranged so
//    gemm_kernel<0> sits at index 3: detect(0), prep(1), sv(2), gemm0(3).
//  - Winning GEMM mainloop (do not touch): 8 warps, 128x128 tile, 4x2 warp
//    grid, K=16 double-buffered sync-load stages (AS_LDH=24), 2 CTAs/SM,
//    fp16 operands + fp32 accum.

// ---------------- problem constants ----------------
#define BQ 4
#define LQ 8192
#define DQ 1024
#define NHQ 16
#define HDQ 64
#define MT (BQ * LQ)          // 32768 rows
#define ROW_TILES (MT / 128)  // 256
#define COL_TILES (DQ / 128)  // 8
#define NT 64                 // k-stages of 16

// ---------------- device scratch (no allocations allowed) ----------------
__device__ __align__(16) __half g_Xh[MT * DQ];       // fp16 copy of query (64MB)
__device__ __align__(16) __half g_Wkh[DQ * DQ];      // fp16 Wk (2MB)
__device__ __align__(16) __half g_Wqh[DQ * DQ];      // fp16 Wq (2MB)
__device__ __align__(16) float g_Wv_sumT[NHQ * DQ];  // [head][k]
__device__ __align__(16) float g_bv_sum[NHQ];
__device__ int   g_mask_kind;
__device__ __align__(16) float g_sv[MT * NHQ];
__device__ __align__(16) float g_partial[ROW_TILES * DQ];
__device__ __align__(16) float g_kv_sum[BQ * DQ];

__device__ __forceinline__ float phi_fn(float x) {
    return x > 0.f ? x + 1.f : __expf(x);   // elu(x)+1
}

__device__ __forceinline__ uint2 pack_half4(float4 v) {
    __half2 h01 = __floats2half2_rn(v.x, v.y);
    __half2 h23 = __floats2half2_rn(v.z, v.w);
    uint2 u;
    u.x = *reinterpret_cast<const uint32_t*>(&h01);
    u.y = *reinterpret_cast<const uint32_t*>(&h23);
    return u;
}

// ---------------- mask dtype detection ----------------
__global__ void detect_mask_kernel(const unsigned int* m) {
    __shared__ int f_nonbin, f_float;
    if (threadIdx.x == 0) { f_nonbin = 0; f_float = 0; }
    __syncthreads();
    int nb = 0, fl = 0;
    for (int i = threadIdx.x; i < 8192; i += 256) {
        unsigned v = m[i];
        if (v == 0x3F800000u) fl = 1;
        else if (v > 1u) nb = 1;
    }
    if (fl) atomicOr(&f_float, 1);
    if (nb) atomicOr(&f_nonbin, 1);
    __syncthreads();
    if (threadIdx.x == 0) g_mask_kind = f_float ? 2 : (f_nonbin ? 1 : 0);
}

// ---------------- prep: Wk/Wq -> fp16 + Wv column sums (one kernel) --------
__global__ void prep_kernel(const float* __restrict__ Wk,
                            const float* __restrict__ Wq,
                            const float* __restrict__ Wv,
                            const float* __restrict__ bv,
                            __half* __restrict__ wkh,
                            __half* __restrict__ wqh) {
    const int b = blockIdx.x, tid = threadIdx.x;
    if (b < 512 || (b >= 512 && b < 1024)) {
        const float* src = (b < 512) ? Wk : Wq;
        __half* dst = (b < 512) ? wkh : wqh;
        int i = (b & 511) * 256 + tid;   // uint4 index (8 halves)
        float4 a = ((const float4*)src)[i * 2];
        float4 c = ((const float4*)src)[i * 2 + 1];
        uint2 u0 = pack_half4(a), u1 = pack_half4(c);
        uint4 u; u.x = u0.x; u.y = u0.y; u.z = u1.x; u.w = u1.y;
        ((uint4*)dst)[i] = u;
    } else {
        int t = (b - 1024) * 256 + tid;
        if (t < DQ * NHQ) {
            int k = t >> 4, n = t & 15;
            const float* p = Wv + (size_t)k * DQ + n * HDQ;
            float s = 0.f;
            #pragma unroll 8
            for (int v = 0; v < HDQ; v++) s += p[v];
            g_Wv_sumT[n * DQ + k] = s;
        }
        if (t < NHQ) {
            const float* p = bv + t * HDQ;
            float s = 0.f;
            #pragma unroll 8
            for (int v = 0; v < HDQ; v++) s += p[v];
            g_bv_sum[t] = s;
        }
    }
}

// ---------------- sv pre-pass + X->fp16 + inline mask ----------------
__global__ void __launch_bounds__(256) sv_kernel(const float* __restrict__ X,
                                                 const void* __restrict__ mask,
                                                 __half* __restrict__ Xh) {
    extern __shared__ __align__(16) float4 sWv[];
    const int tid = threadIdx.x;
    {
        const float4* src = (const float4*)g_Wv_sumT;
        #pragma unroll
        for (int i = 0; i < NHQ * DQ / 4 / 256; i++)
            sWv[i * 256 + tid] = src[i * 256 + tid];
    }
    __syncthreads();

    const int warp = tid >> 5, lane = tid & 31;
    const int row0 = blockIdx.x * 16 + warp * 2;
    const float4* x0 = (const float4*)(X + (size_t)row0 * DQ);
    const float4* x1 = (const float4*)(X + (size_t)(row0 + 1) * DQ);
    uint2* xh0 = (uint2*)(Xh + (size_t)row0 * DQ);
    uint2* xh1 = (uint2*)(Xh + (size_t)(row0 + 1) * DQ);

    float acc[2][NHQ];
    #pragma unroll
    for (int p = 0; p < 2; p++)
        #pragma unroll
        for (int h = 0; h < NHQ; h++) acc[p][h] = 0.f;

    for (int c = lane; c < DQ / 4; c += 32) {
        float4 xv0 = x0[c], xv1 = x1[c];
        xh0[c] = pack_half4(xv0);            // fused fp16 writeout
        xh1[c] = pack_half4(xv1);
        #pragma unroll
        for (int h = 0; h < NHQ; h++) {
            float4 w = sWv[h * (DQ / 4) + c];
            acc[0][h] += xv0.x * w.x + xv0.y * w.y + xv0.z * w.z + xv0.w * w.w;
            acc[1][h] += xv1.x * w.x + xv1.y * w.y + xv1.z * w.z + xv1.w * w.w;
        }
    }
    #pragma unroll
    for (int off = 16; off; off >>= 1)
        #pragma unroll
        for (int p = 0; p < 2; p++)
            #pragma unroll
            for (int h = 0; h < NHQ; h++)
                acc[p][h] += __shfl_xor_sync(0xffffffffu, acc[p][h], off);
    if (lane < NHQ) {
        const int kind = g_mask_kind;
        float bvs = g_bv_sum[lane];
        #pragma unroll
        for (int p = 0; p < 2; p++) {
            const int row = row0 + p;
            int m;
            if (kind == 2)      m = (((const float*)mask)[row] != 0.0f);
            else if (kind == 1) m = (((const unsigned char*)mask)[row] != 0);
            else                m = (((const int*)mask)[row] != 0);
            g_sv[(size_t)row * NHQ + lane] = m ? 0.f : acc[p][lane] + bvs;
        }
    }
}

// ---------------- main GEMM: K=16 stages (proven), single-pass epilogue ----
#define AS_LDH 24
#define BS_LDH 136
#define A_STG_H (128 * AS_LDH)               // 3072 halves
#define B_STG_H (16 * BS_LDH)                // 2176 halves
#define B_BASE_H (2 * A_STG_H)               // 6144
#define CT_LD 132
#define GSMEM_B (128 * CT_LD * 4)            // 67584 B (union covers stages)

template <int MODE>
__global__ void __launch_bounds__(256, 2)
gemm_kernel(const __half* __restrict__ Xh, const __half* __restrict__ Wh,
            const float* __restrict__ bias, float* __restrict__ outp) {
    extern __shared__ __align__(16) char ds[];
    __half* hs = (__half*)ds;            // stages
    float*  Ct = (float*)ds;             // epilogue union (128 x 132)
    __shared__ float svred[256];
    __shared__ float red2[256];

    const int tid = threadIdx.x;
    const int bn = blockIdx.x;   // column tile (128 cols = 2 heads)
    const int br = blockIdx.y;   // row tile

    const __half* Ab = Xh + (size_t)br * 128 * DQ;
    const __half* Bb = Wh + bn * 128;

    // A staging: thread owns row arow, 8 halves at aseg
    const int arow = tid >> 1, aseg = (tid & 1) * 8;
    // B staging: thread owns row brow, 8 halves at bseg
    const int brow = tid >> 4, bseg = (tid & 15) * 8;
    const __half* srcA = Ab + (size_t)arow * DQ + aseg;
    const __half* srcB = Bb + (size_t)brow * DQ + bseg;
    __half* dstA = hs + arow * AS_LDH + aseg;
    __half* dstB = hs + B_BASE_H + brow * BS_LDH + bseg;

    const int wid = tid >> 5;
    const int wm = wid & 3;       // warp rows wm*32 .. +31
    const int wn = wid >> 2;      // warp cols wn*64 .. +63

    wmma::fragment<wmma::accumulator, 16, 16, 16, float> fc[2][4];
    #pragma unroll
    for (int i = 0; i < 2; i++)
        #pragma unroll
        for (int j = 0; j < 4; j++)
            wmma::fill_fragment(fc[i][j], 0.f);

    // ---- preload stage 0 ----
    {
        uint4 a = *(const uint4*)(srcA);
        uint4 b = *(const uint4*)(srcB);
        *(uint4*)dstA = a;
        *(uint4*)dstB = b;
    }
    __syncthreads();

    int buf = 0;
    for (int t = 0; t < NT; t++) {
        uint4 na, nb;
        if (t < NT - 1) {
            const int ko = (t + 1) * 16;
            na = *(const uint4*)(srcA + ko);
            nb = *(const uint4*)(srcB + (size_t)ko * DQ);
        }

        // compute on stage[buf]: one K=16 wmma step
        {
            const __half* As = hs + buf * A_STG_H;
            const __half* Bs = hs + B_BASE_H + buf * B_STG_H;
            wmma::fragment<wmma::matrix_a, 16, 16, 16, __half, wmma::row_major> fa[2];
            wmma::fragment<wmma::matrix_b, 16, 16, 16, __half, wmma::row_major> fb[4];
            #pragma unroll
            for (int i = 0; i < 2; i++)
                wmma::load_matrix_sync(fa[i], As + (wm * 32 + i * 16) * AS_LDH, AS_LDH);
            #pragma unroll
            for (int j = 0; j < 4; j++)
                wmma::load_matrix_sync(fb[j], Bs + wn * 64 + j * 16, BS_LDH);
            #pragma unroll
            for (int i = 0; i < 2; i++)
                #pragma unroll
                for (int j = 0; j < 4; j++)
                    wmma::mma_sync(fc[i][j], fa[i], fb[j], fc[i][j]);
        }

        if (t < NT - 1) {
            const int nbuf = buf ^ 1;
            *(uint4*)(dstA + nbuf * A_STG_H) = na;
            *(uint4*)(dstB + nbuf * B_STG_H) = nb;
        }
        __syncthreads();
        buf ^= 1;
    }
    __syncthreads();

    // ---- single-pass epilogue: all fragments -> Ct (128 x 132) ----
    if (MODE == 0) {
        if (tid < 128) {
            float2 s = *(const float2*)(g_sv + (size_t)(br * 128 + tid) * NHQ + bn * 2);
            svred[tid * 2 + 0] = s.x;
            svred[tid * 2 + 1] = s.y;
        }
    }
    #pragma unroll
    for (int i = 0; i < 2; i++)
        #pragma unroll
        for (int j = 0; j < 4; j++)
            wmma::store_matrix_sync(&Ct[(wm * 32 + i * 16) * CT_LD + wn * 64 + j * 16],
                                    fc[i][j], CT_LD, wmma::mem_row_major);
    __syncthreads();

    const int c = tid & 127, rg = tid >> 7;   // rg in {0,1}
    const float bias_c = bias[bn * 128 + c];
    if (MODE == 0) {
        const int hh = c >> 6;
        float part = 0.f;
        #pragma unroll 8
        for (int r = rg; r < 128; r += 2)
            part += phi_fn(Ct[r * CT_LD + c] + bias_c) * svred[r * 2 + hh];
        red2[rg * 128 + c] = part;
        __syncthreads();
        if (tid < 128)
            g_partial[(size_t)br * DQ + bn * 128 + tid] = red2[tid] + red2[128 + tid];
    } else {
        const int gcol = bn * 128 + c;
        const float kvs = g_kv_sum[(br >> 6) * DQ + gcol];
        #pragma unroll 8
        for (int r = rg; r < 128; r += 2)
            outp[(size_t)(br * 128 + r) * DQ + gcol] =
                phi_fn(Ct[r * CT_LD + c] + bias_c) * kvs;
    }
}

// ---------------- deterministic reduction of per-tile partials ----------------
__global__ void kvreduce_kernel() {
    int t = blockIdx.x * 256 + threadIdx.x;
    if (t >= BQ * DQ) return;
    int b = t >> 10, c = t & 1023;
    const float* p = g_partial + (size_t)(b * 64) * DQ + c;
    float s = 0.f;
    #pragma unroll 8
    for (int j = 0; j < 64; j++) s += p[(size_t)j * DQ];
    g_kv_sum[t] = s;
}

// ---------------- entry point ----------------
extern "C" void kernel_launch(void* const* d_in, const int* in_sizes, int n_in,
                              void* d_out, int out_size) {
    const float* query = (const float*)d_in[0];
    const void*  mask  = d_in[1];
    const float* Wq    = (const float*)d_in[2];
    const float* bq    = (const float*)d_in[3];
    const float* Wk    = (const float*)d_in[4];
    const float* bk    = (const float*)d_in[5];
    const float* Wv    = (const float*)d_in[6];
    const float* bv    = (const float*)d_in[7];
    float* out = (float*)d_out;

    __half* xh;  cudaGetSymbolAddress((void**)&xh,  g_Xh);
    __half* wkh; cudaGetSymbolAddress((void**)&wkh, g_Wkh);
    __half* wqh; cudaGetSymbolAddress((void**)&wqh, g_Wqh);

    const int sv_smem = NHQ * DQ * 4;   // 64KB
    cudaFuncSetAttribute(sv_kernel, cudaFuncAttributeMaxDynamicSharedMemorySize, sv_smem);
    cudaFuncSetAttribute(gemm_kernel<0>, cudaFuncAttributeMaxDynamicSharedMemorySize, GSMEM_B);
    cudaFuncSetAttribute(gemm_kernel<1>, cudaFuncAttributeMaxDynamicSharedMemorySize, GSMEM_B);

    // Launch order arranged so gemm_kernel<0> is at index 3 (ncu target).
    detect_mask_kernel<<<1, 256>>>((const unsigned int*)mask);             // 0
    prep_kernel<<<1024 + 64, 256>>>(Wk, Wq, Wv, bv, wkh, wqh);             // 1
    sv_kernel<<<MT / 16, 256, sv_smem>>>(query, mask, xh);                 // 2
    gemm_kernel<0><<<dim3(COL_TILES, ROW_TILES), 256, GSMEM_B>>>(xh, wkh, bk, nullptr); // 3
    kvreduce_kernel<<<(BQ * DQ + 255) / 256, 256>>>();                     // 4
    gemm_kernel<1><<<dim3(COL_TILES, ROW_TILES), 256, GSMEM_B>>>(xh, wqh, bq, out);     // 5
}

// round 17
// speedup vs baseline: 1.0769x; 1.0021x over previous
#include <cuda_runtime.h>
#include <cuda_fp16.h>
#include <mma.h>
#include <cstdint>

using namespace nvcuda;

// NOTE (environment pitfalls, confirmed):
//  - Harness PTX targets sm_103 (no 'a'): tcgen05/TMEM rejected by ptxas.
//    Legacy mma.sync (HMMA) is the usable tensor engine.
//  - Static __device__ scratch: 68MB passes, 142MB poisons. Stay <100MB.
//  - ncu profiles the launch at INDEX 3; launch order keeps gemm0 there.
//  - R16 ncu on gemm: tensor=42.9%, L1=83.7% -> smem-pipe bound. This round:
//    conflict-free A staging + cp.async (1 barrier/stage) to cut L1 traffic.

// ---------------- problem constants ----------------
#define BQ 4
#define LQ 8192
#define DQ 1024
#define NHQ 16
#define HDQ 64
#define MT (BQ * LQ)          // 32768 rows
#define ROW_TILES (MT / 128)  // 256
#define COL_TILES (DQ / 128)  // 8
#define NT 64                 // k-stages of 16

// ---------------- device scratch (no allocations allowed) ----------------
__device__ __align__(16) __half g_Xh[MT * DQ];       // fp16 copy of query (64MB)
__device__ __align__(16) __half g_Wkh[DQ * DQ];      // fp16 Wk (2MB)
__device__ __align__(16) __half g_Wqh[DQ * DQ];      // fp16 Wq (2MB)
__device__ __align__(16) float g_Wv_sumT[NHQ * DQ];  // [head][k]
__device__ __align__(16) float g_bv_sum[NHQ];
__device__ int   g_mask_kind;
__device__ __align__(16) float g_sv[MT * NHQ];
__device__ __align__(16) float g_partial[ROW_TILES * DQ];
__device__ __align__(16) float g_kv_sum[BQ * DQ];

__device__ __forceinline__ float phi_fn(float x) {
    return x > 0.f ? x + 1.f : __expf(x);   // elu(x)+1
}

__device__ __forceinline__ uint2 pack_half4(float4 v) {
    __half2 h01 = __floats2half2_rn(v.x, v.y);
    __half2 h23 = __floats2half2_rn(v.z, v.w);
    uint2 u;
    u.x = *reinterpret_cast<const uint32_t*>(&h01);
    u.y = *reinterpret_cast<const uint32_t*>(&h23);
    return u;
}

// ---------------- mask dtype detection ----------------
__global__ void detect_mask_kernel(const unsigned int* m) {
    __shared__ int f_nonbin, f_float;
    if (threadIdx.x == 0) { f_nonbin = 0; f_float = 0; }
    __syncthreads();
    int nb = 0, fl = 0;
    for (int i = threadIdx.x; i < 8192; i += 256) {
        unsigned v = m[i];
        if (v == 0x3F800000u) fl = 1;
        else if (v > 1u) nb = 1;
    }
    if (fl) atomicOr(&f_float, 1);
    if (nb) atomicOr(&f_nonbin, 1);
    __syncthreads();
    if (threadIdx.x == 0) g_mask_kind = f_float ? 2 : (f_nonbin ? 1 : 0);
}

// ---------------- prep: Wk/Wq -> fp16 + Wv column sums (one kernel) --------
__global__ void prep_kernel(const float* __restrict__ Wk,
                            const float* __restrict__ Wq,
                            const float* __restrict__ Wv,
                            const float* __restrict__ bv,
                            __half* __restrict__ wkh,
                            __half* __restrict__ wqh) {
    const int b = blockIdx.x, tid = threadIdx.x;
    if (b < 1024) {
        const float* src = (b < 512) ? Wk : Wq;
        __half* dst = (b < 512) ? wkh : wqh;
        int i = (b & 511) * 256 + tid;   // uint4 index (8 halves)
        float4 a = ((const float4*)src)[i * 2];
        float4 c = ((const float4*)src)[i * 2 + 1];
        uint2 u0 = pack_half4(a), u1 = pack_half4(c);
        uint4 u; u.x = u0.x; u.y = u0.y; u.z = u1.x; u.w = u1.y;
        ((uint4*)dst)[i] = u;
    } else {
        int t = (b - 1024) * 256 + tid;
        if (t < DQ * NHQ) {
            int k = t >> 4, n = t & 15;
            const float* p = Wv + (size_t)k * DQ + n * HDQ;
            float s = 0.f;
            #pragma unroll 8
            for (int v = 0; v < HDQ; v++) s += p[v];
            g_Wv_sumT[n * DQ + k] = s;
        }
        if (t < NHQ) {
            const float* p = bv + t * HDQ;
            float s = 0.f;
            #pragma unroll 8
            for (int v = 0; v < HDQ; v++) s += p[v];
            g_bv_sum[t] = s;
        }
    }
}

// ---------------- sv pre-pass + X->fp16 + inline mask ----------------
__global__ void __launch_bounds__(256) sv_kernel(const float* __restrict__ X,
                                                 const void* __restrict__ mask,
                                                 __half* __restrict__ Xh) {
    extern __shared__ __align__(16) float4 sWv[];
    const int tid = threadIdx.x;
    {
        const float4* src = (const float4*)g_Wv_sumT;
        #pragma unroll
        for (int i = 0; i < NHQ * DQ / 4 / 256; i++)
            sWv[i * 256 + tid] = src[i * 256 + tid];
    }
    __syncthreads();

    const int warp = tid >> 5, lane = tid & 31;
    const int row0 = blockIdx.x * 16 + warp * 2;
    const float4* x0 = (const float4*)(X + (size_t)row0 * DQ);
    const float4* x1 = (const float4*)(X + (size_t)(row0 + 1) * DQ);
    uint2* xh0 = (uint2*)(Xh + (size_t)row0 * DQ);
    uint2* xh1 = (uint2*)(Xh + (size_t)(row0 + 1) * DQ);

    float acc[2][NHQ];
    #pragma unroll
    for (int p = 0; p < 2; p++)
        #pragma unroll
        for (int h = 0; h < NHQ; h++) acc[p][h] = 0.f;

    for (int c = lane; c < DQ / 4; c += 32) {
        float4 xv0 = x0[c], xv1 = x1[c];
        xh0[c] = pack_half4(xv0);            // fused fp16 writeout
        xh1[c] = pack_half4(xv1);
        #pragma unroll
        for (int h = 0; h < NHQ; h++) {
            float4 w = sWv[h * (DQ / 4) + c];
            acc[0][h] += xv0.x * w.x + xv0.y * w.y + xv0.z * w.z + xv0.w * w.w;
            acc[1][h] += xv1.x * w.x + xv1.y * w.y + xv1.z * w.z + xv1.w * w.w;
        }
    }
    #pragma unroll
    for (int off = 16; off; off >>= 1)
        #pragma unroll
        for (int p = 0; p < 2; p++)
            #pragma unroll
            for (int h = 0; h < NHQ; h++)
                acc[p][h] += __shfl_xor_sync(0xffffffffu, acc[p][h], off);
    if (lane < NHQ) {
        const int kind = g_mask_kind;
        float bvs = g_bv_sum[lane];
        #pragma unroll
        for (int p = 0; p < 2; p++) {
            const int row = row0 + p;
            int m;
            if (kind == 2)      m = (((const float*)mask)[row] != 0.0f);
            else if (kind == 1) m = (((const unsigned char*)mask)[row] != 0);
            else                m = (((const int*)mask)[row] != 0);
            g_sv[(size_t)row * NHQ + lane] = m ? 0.f : acc[p][lane] + bvs;
        }
    }
}

// ---------------- main GEMM: K=16, cp.async 4-stage, conflict-free A -------
#define AS_LDH 24
#define BS_LDH 136
#define A_STG_H (128 * AS_LDH)               // 3072 halves = 6144 B
#define B_STG_H (16 * BS_LDH)                // 2176 halves = 4352 B
#define B_BASE_H (4 * A_STG_H)               // A stages first, then B stages
#define CT_LD 132
#define GSMEM_B (128 * CT_LD * 4)            // 67584 B (> stages 41984 B)

__device__ __forceinline__ void cp16(uint32_t dst, const void* src) {
    asm volatile("cp.async.cg.shared.global [%0], [%1], 16;" :: "r"(dst), "l"(src));
}
__device__ __forceinline__ void cp_commit() {
    asm volatile("cp.async.commit_group;");
}
__device__ __forceinline__ void cp_wait2() {
    asm volatile("cp.async.wait_group 2;");
}
__device__ __forceinline__ void cp_wait0() {
    asm volatile("cp.async.wait_group 0;");
}

template <int MODE>
__global__ void __launch_bounds__(256, 2)
gemm_kernel(const __half* __restrict__ Xh, const __half* __restrict__ Wh,
            const float* __restrict__ bias, float* __restrict__ outp) {
    extern __shared__ __align__(16) char ds[];
    __half* hs = (__half*)ds;            // stages
    float*  Ct = (float*)ds;             // epilogue union (128 x 132)
    __shared__ float svred[256];
    __shared__ float red2[256];

    const int tid = threadIdx.x;
    const int bn = blockIdx.x;   // column tile (128 cols = 2 heads)
    const int br = blockIdx.y;   // row tile

    const __half* Ab = Xh + (size_t)br * 128 * DQ;
    const __half* Bb = Wh + bn * 128;

    // A staging (conflict-free): thread owns row (tid&127), chunk (tid>>7)
    const int arow = tid & 127, achk = (tid >> 7) * 8;
    // B staging: thread owns k-row (tid>>4), 8 halves at (tid&15)*8
    const int brow = tid >> 4, bseg = (tid & 15) * 8;
    const __half* srcA = Ab + (size_t)arow * DQ + achk;
    const __half* srcB = Bb + (size_t)brow * DQ + bseg;

    const uint32_t smem_base = (uint32_t)__cvta_generic_to_shared(hs);
    const uint32_t dA = smem_base + (uint32_t)(arow * AS_LDH + achk) * 2u;
    const uint32_t dB = smem_base + (uint32_t)(B_BASE_H + brow * BS_LDH + bseg) * 2u;

    #define ISSUE_STAGE(slot, kt) do {                                        \
        cp16(dA + (uint32_t)(slot) * (A_STG_H * 2u), srcA + (kt));            \
        cp16(dB + (uint32_t)(slot) * (B_STG_H * 2u), srcB + (size_t)(kt) * DQ); \
        cp_commit(); } while (0)

    ISSUE_STAGE(0, 0);
    ISSUE_STAGE(1, 16);
    ISSUE_STAGE(2, 32);

    const int wid = tid >> 5;
    const int wm = wid & 3;       // warp rows wm*32 .. +31
    const int wn = wid >> 2;      // warp cols wn*64 .. +63

    wmma::fragment<wmma::accumulator, 16, 16, 16, float> fc[2][4];
    #pragma unroll
    for (int i = 0; i < 2; i++)
        #pragma unroll
        for (int j = 0; j < 4; j++)
            wmma::fill_fragment(fc[i][j], 0.f);

    for (int t = 0; t < NT; t++) {
        cp_wait2();
        __syncthreads();      // stage t visible to all threads
        if (t + 3 < NT) {
            ISSUE_STAGE((t + 3) & 3, (t + 3) * 16);   // writes buffer (t-1)&3: drained
        } else {
            cp_commit();      // empty group keeps wait_group accounting uniform
        }

        const __half* As = hs + (t & 3) * A_STG_H;
        const __half* Bs = hs + B_BASE_H + (t & 3) * B_STG_H;
        wmma::fragment<wmma::matrix_a, 16, 16, 16, __half, wmma::row_major> fa[2];
        wmma::fragment<wmma::matrix_b, 16, 16, 16, __half, wmma::row_major> fb[4];
        #pragma unroll
        for (int i = 0; i < 2; i++)
            wmma::load_matrix_sync(fa[i], As + (wm * 32 + i * 16) * AS_LDH, AS_LDH);
        #pragma unroll
        for (int j = 0; j < 4; j++)
            wmma::load_matrix_sync(fb[j], Bs + wn * 64 + j * 16, BS_LDH);
        #pragma unroll
        for (int i = 0; i < 2; i++)
            #pragma unroll
            for (int j = 0; j < 4; j++)
                wmma::mma_sync(fc[i][j], fa[i], fb[j], fc[i][j]);
    }
    cp_wait0();               // drain empty groups before Ct aliases the stages
    __syncthreads();

    // ---- single-pass epilogue: all fragments -> Ct (128 x 132) ----
    if (MODE == 0) {
        if (tid < 128) {
            float2 s = *(const float2*)(g_sv + (size_t)(br * 128 + tid) * NHQ + bn * 2);
            svred[tid * 2 + 0] = s.x;
            svred[tid * 2 + 1] = s.y;
        }
    }
    #pragma unroll
    for (int i = 0; i < 2; i++)
        #pragma unroll
        for (int j = 0; j < 4; j++)
            wmma::store_matrix_sync(&Ct[(wm * 32 + i * 16) * CT_LD + wn * 64 + j * 16],
                                    fc[i][j], CT_LD, wmma::mem_row_major);
    __syncthreads();

    const int c = tid & 127, rg = tid >> 7;   // rg in {0,1}
    const float bias_c = bias[bn * 128 + c];
    if (MODE == 0) {
        const int hh = c >> 6;
        float part = 0.f;
        #pragma unroll 8
        for (int r = rg; r < 128; r += 2)
            part += phi_fn(Ct[r * CT_LD + c] + bias_c) * svred[r * 2 + hh];
        red2[rg * 128 + c] = part;
        __syncthreads();
        if (tid < 128)
            g_partial[(size_t)br * DQ + bn * 128 + tid] = red2[tid] + red2[128 + tid];
    } else {
        const int gcol = bn * 128 + c;
        const float kvs = g_kv_sum[(br >> 6) * DQ + gcol];
        #pragma unroll 8
        for (int r = rg; r < 128; r += 2)
            outp[(size_t)(br * 128 + r) * DQ + gcol] =
                phi_fn(Ct[r * CT_LD + c] + bias_c) * kvs;
    }
    #undef ISSUE_STAGE
}

// ---------------- deterministic reduction of per-tile partials ----------------
__global__ void kvreduce_kernel() {
    int t = blockIdx.x * 256 + threadIdx.x;
    if (t >= BQ * DQ) return;
    int b = t >> 10, c = t & 1023;
    const float* p = g_partial + (size_t)(b * 64) * DQ + c;
    float s = 0.f;
    #pragma unroll 8
    for (int j = 0; j < 64; j++) s += p[(size_t)j * DQ];
    g_kv_sum[t] = s;
}

// ---------------- entry point ----------------
extern "C" void kernel_launch(void* const* d_in, const int* in_sizes, int n_in,
                              void* d_out, int out_size) {
    const float* query = (const float*)d_in[0];
    const void*  mask  = d_in[1];
    const float* Wq    = (const float*)d_in[2];
    const float* bq    = (const float*)d_in[3];
    const float* Wk    = (const float*)d_in[4];
    const float* bk    = (const float*)d_in[5];
    const float* Wv    = (const float*)d_in[6];
    const float* bv    = (const float*)d_in[7];
    float* out = (float*)d_out;

    __half* xh;  cudaGetSymbolAddress((void**)&xh,  g_Xh);
    __half* wkh; cudaGetSymbolAddress((void**)&wkh, g_Wkh);
    __half* wqh; cudaGetSymbolAddress((void**)&wqh, g_Wqh);

    const int sv_smem = NHQ * DQ * 4;   // 64KB
    cudaFuncSetAttribute(sv_kernel, cudaFuncAttributeMaxDynamicSharedMemorySize, sv_smem);
    cudaFuncSetAttribute(gemm_kernel<0>, cudaFuncAttributeMaxDynamicSharedMemorySize, GSMEM_B);
    cudaFuncSetAttribute(gemm_kernel<1>, cudaFuncAttributeMaxDynamicSharedMemorySize, GSMEM_B);

    // Launch order arranged so gemm_kernel<0> is at index 3 (ncu target).
    detect_mask_kernel<<<1, 256>>>((const unsigned int*)mask);             // 0
    prep_kernel<<<1024 + 64, 256>>>(Wk, Wq, Wv, bv, wkh, wqh);             // 1
    sv_kernel<<<MT / 16, 256, sv_smem>>>(query, mask, xh);                 // 2
    gemm_kernel<0><<<dim3(COL_TILES, ROW_TILES), 256, GSMEM_B>>>(xh, wkh, bk, nullptr); // 3
    kvreduce_kernel<<<(BQ * DQ + 255) / 256, 256>>>();                     // 4
    gemm_kernel<1><<<dim3(COL_TILES, ROW_TILES), 256, GSMEM_B>>>(xh, wqh, bq, out);     // 5
}